// round 5
// baseline (speedup 1.0000x reference)
#include <cuda_runtime.h>
#include <cuda_fp16.h>
#include <cuda_fp8.h>
#include <cstdint>

#define VOCAB 32000
#define NS 10
#define BB 256
#define TT 2048
#define CHUNKS 16
#define CLEN 128                // TT / CHUNKS
#define WARM 8                  // burn-in steps (contraction ~0.27/step)
#define DEPTH 8                 // software pipeline depth
#define NGROUP (BB * CHUNKS)    // 4096 independent chains
#define NBLK (NGROUP / 4)       // 1024 blocks, 4 chains each
#define STAGE_N (WARM + CLEN + DEPTH)   // 144

// Fused per-vocab table, fp8 e4m3, 128B-aligned rows (1 line, 4 sectors):
//  row layout: [8j .. 8j+8)   : col j, k=0..7 as 4 fp8x2 k-pairs   (j=0..10)
//              [88+2j..88+2j+2): col j, (k8,k9) fp8x2 pair
//  col j<10 : c[k][j] = E_v[k] * M_v[k][j];  col 10: E_v[k]
// E_v[k] = exp(emb[v,k]-colLSE[k]+15ln2); M_v = row-softmax(transition*f_v)
__device__ alignas(128) uint4 g_T8[VOCAB * 8];
__device__ float g_plse[80];
__device__ float g_part[NBLK];
__device__ unsigned g_done;

// ---------------------------------------------------------------------------
// K1: partial column sums of exp(emb) over vocab slices. grid (8, 10).
// ---------------------------------------------------------------------------
__global__ void k_collse(const float* __restrict__ emb) {
    if (blockIdx.x == 0 && blockIdx.y == 0 && threadIdx.x == 0) g_done = 0;
    int s = blockIdx.y, part = blockIdx.x;
    int start = part * (VOCAB / 8);
    float sum = 0.f;
    for (int i = threadIdx.x; i < VOCAB / 8; i += 256)
        sum += __expf(emb[(start + i) * NS + s]);
    __shared__ float red[256];
    red[threadIdx.x] = sum;
    __syncthreads();
    for (int o = 128; o > 0; o >>= 1) {
        if (threadIdx.x < o) red[threadIdx.x] += red[threadIdx.x + o];
        __syncthreads();
    }
    if (threadIdx.x == 0) g_plse[s * 8 + part] = red[0];
}

// exp(x) for |x| <= 0.5 (rel err ~3.6e-5)
__device__ __forceinline__ float exp_poly(float x) {
    float r = fmaf(x, 1.f / 120.f, 1.f / 24.f);
    r = fmaf(r, x, 1.f / 6.f);
    r = fmaf(r, x, 0.5f);
    r = fmaf(r, x, 1.f);
    r = fmaf(r, x, 1.f);
    return r;
}

__device__ __forceinline__ unsigned to_f8(float x) {
    return (unsigned)__nv_cvt_float_to_fp8(x, __NV_SATFINITE, __NV_E4M3);
}

// ---------------------------------------------------------------------------
// K2: build fused fp8 tables. 2 threads per vocab id.
//   half 0: columns j=0..4 ;  half 1: columns j=5..9 and E column (j=10)
// ---------------------------------------------------------------------------
__global__ void k_build(const float* __restrict__ emb,
                        const float* __restrict__ trans,
                        const float* __restrict__ gw,
                        const float* __restrict__ gb) {
    __shared__ float s_tr[100], s_gw[100], s_gb[10], s_lse[10];
    int tid = threadIdx.x;
    if (tid < 100) { s_tr[tid] = trans[tid]; s_gw[tid] = gw[tid]; }
    if (tid < 10) {
        s_gb[tid] = gb[tid];
        float t = 0.f;
#pragma unroll
        for (int p = 0; p < 8; p++) t += g_plse[tid * 8 + p];
        s_lse[tid] = logf(t);
    }
    __syncthreads();

    int gidt = blockIdx.x * blockDim.x + tid;
    int v = gidt >> 1, half = gidt & 1;
    if (v >= VOCAB) return;

    float eb[10];
#pragma unroll
    for (int k = 0; k < 10; k++) eb[k] = emb[v * NS + k];

    const float LN2 = 0.6931471805599453f;
    float Ev[10];
#pragma unroll
    for (int j = 0; j < 10; j++)
        Ev[j] = __expf(eb[j] - s_lse[j] + 15.f * LN2);

    // gate: f_s = sigmoid(emb . gate_w[s,:] + gate_b[s])
    float f[10];
#pragma unroll
    for (int s = 0; s < 10; s++) {
        float g = s_gb[s];
#pragma unroll
        for (int k = 0; k < 10; k++) g = fmaf(eb[k], s_gw[s * 10 + k], g);
        f[s] = 1.f / (1.f + __expf(-g));
    }

    // row-softmax denominators fused with Ev
    float scale[10];
#pragma unroll
    for (int k = 0; k < 10; k++) {
        float rs = 0.f;
#pragma unroll
        for (int j = 0; j < 10; j++) rs += exp_poly(s_tr[k * 10 + j] * f[j]);
        scale[k] = Ev[k] * __fdividef(1.f, rs);
    }

    char* row = (char*)g_T8 + ((unsigned)v << 7);
    int j0 = half ? 5 : 0, j1 = half ? 10 : 5;
    for (int j = j0; j < j1; j++) {
        unsigned b[10];
#pragma unroll
        for (int k = 0; k < 10; k++)
            b[k] = to_f8(exp_poly(s_tr[k * 10 + j] * f[j]) * scale[k]);
        uint2 w;
        w.x = b[0] | (b[1] << 8) | (b[2] << 16) | (b[3] << 24);
        w.y = b[4] | (b[5] << 8) | (b[6] << 16) | (b[7] << 24);
        *(uint2*)(row + 8 * j) = w;
        *(unsigned short*)(row + 88 + 2 * j) = (unsigned short)(b[8] | (b[9] << 8));
    }
    if (half) {  // E column (j = 10)
        unsigned b[10];
#pragma unroll
        for (int k = 0; k < 10; k++) b[k] = to_f8(Ev[k]);
        uint2 w;
        w.x = b[0] | (b[1] << 8) | (b[2] << 16) | (b[3] << 24);
        w.y = b[4] | (b[5] << 8) | (b[6] << 16) | (b[7] << 24);
        *(uint2*)(row + 80) = w;
        *(unsigned short*)(row + 108) = (unsigned short)(b[8] | (b[9] << 8));
    }
}

// ---------------------------------------------------------------------------
// K3: chunked scan, half2 datapath. 64-thr blocks, 2 warps, 2 chains/warp
// (lanes 0-10 / 16-26). Lane r (<10): state u_r; lane r==10: S = Sum u_k E_k.
// Pair-broadcast: 1 shfl_xor + pack, then 5 half2 shfls; 5 HFMA2 matvec.
// Final reduction folded in via atomic ticket (fixed-order sum).
// ---------------------------------------------------------------------------
__device__ __forceinline__ __half2 f8h(unsigned s) {
    __half2_raw hr = __nv_cvt_fp8x2_to_halfraw2((__nv_fp8x2_storage_t)s, __NV_E4M3);
    return *(__half2*)&hr;
}

#define FETCH(st, t_)                                                        \
    {                                                                        \
        int2 tm_ = s_tm[cl][(t_) - t0];                                      \
        mk[st] = __int_as_float(tm_.y);                                      \
        if (act) {                                                           \
            const char* bp_ = (const char*)g_T8 + ((unsigned)tm_.x << 7);    \
            Pm[st] = *(const uint2*)(bp_ + 8 * r);                           \
            Pe[st] = *(const unsigned short*)(bp_ + 88 + 2 * r);             \
        }                                                                    \
    }

#define STEP(st, DOACC, DOREN, tn)                                           \
    {                                                                        \
        const unsigned FULL = 0xffffffffu;                                   \
        int sb_ = lane & 16;                                                 \
        float pu_ = __shfl_xor_sync(FULL, u, 1);                             \
        float lo_ = (lane & 1) ? pu_ : u;                                    \
        float hi_ = (lane & 1) ? u : pu_;                                    \
        __half2 hp_ = __floats2half2_rn(lo_, hi_);                           \
        unsigned hb_ = *(unsigned*)&hp_;                                     \
        unsigned H0 = __shfl_sync(FULL, hb_, sb_ + 0);                       \
        unsigned H1 = __shfl_sync(FULL, hb_, sb_ + 2);                       \
        unsigned H2 = __shfl_sync(FULL, hb_, sb_ + 4);                       \
        unsigned H3 = __shfl_sync(FULL, hb_, sb_ + 6);                       \
        unsigned H4 = __shfl_sync(FULL, hb_, sb_ + 8);                       \
        __half2 a_ = __hmul2(*(__half2*)&H0, f8h(Pm[st].x & 0xffffu));       \
        a_ = __hfma2(*(__half2*)&H1, f8h(Pm[st].x >> 16), a_);               \
        a_ = __hfma2(*(__half2*)&H2, f8h(Pm[st].y & 0xffffu), a_);           \
        a_ = __hfma2(*(__half2*)&H3, f8h(Pm[st].y >> 16), a_);               \
        a_ = __hfma2(*(__half2*)&H4, f8h((unsigned)Pe[st]), a_);             \
        float S = __half2float(__low2half(a_)) + __half2float(__high2half(a_)); \
        float ls = __log2f(S);                                               \
        if (DOACC) acc = fmaf(mk[st], (ls - ls_prev) - 15.0f, acc);          \
        if (DOREN) {                                                         \
            float sv = __shfl_sync(FULL, S, sb_ + 10);                       \
            int Ee = ((__float_as_int(sv) >> 23) & 255) - 127;               \
            u = S * __int_as_float((unsigned)(127 - Ee) << 23);              \
            ls_prev = ls - (float)Ee;                                        \
        } else {                                                             \
            u = S;                                                           \
            ls_prev = ls;                                                    \
        }                                                                    \
        FETCH(st, tn)                                                        \
    }

__global__ void __launch_bounds__(64)
k_scan(const int* __restrict__ sent, const float* __restrict__ masks,
       const float* __restrict__ beg, float* __restrict__ out) {
    __shared__ int2  s_tm[4][STAGE_N];
    __shared__ float s_red[4];
    __shared__ float s_sum[64];
    __shared__ bool  s_flag;

    int tid = threadIdx.x;
    int lane = tid & 31;
    int cl = tid >> 4;                       // chain-local id 0..3
    int r = lane & 15;

    // ---- stage tokens + masks for this block's 4 chains ----
    {
        int c = tid >> 4, i0 = tid & 15;
        int gid_c = blockIdx.x * 4 + c;
        int row_c = gid_c >> 4;              // / CHUNKS
        int t0_c = (gid_c & (CHUNKS - 1)) * CLEN - WARM;
        const int*   tr = sent  + (long)row_c * TT;
        const float* mr = masks + (long)row_c * TT;
        for (int i = i0; i < STAGE_N; i += 16) {
            int g = t0_c + i;
            g = (g < 0) ? 0 : ((g > TT - 1) ? TT - 1 : g);
            s_tm[c][i] = make_int2(tr[g], __float_as_int(mr[g]));
        }
    }
    __syncthreads();

    int gid = blockIdx.x * 4 + cl;
    int ci = gid & (CHUNKS - 1);
    int t0 = ci * CLEN - WARM;

    // exact start state for chunk 0
    float u0v = 0.f, s0 = 0.f;
#pragma unroll
    for (int j = 0; j < NS; j++) {
        float e = __expf(beg[j]);
        s0 += e;
        if (r == j) u0v = e;
    }
    float ls0 = __log2f(s0);

    const bool act = (r < 11);

    uint2 Pm[DEPTH];
    unsigned short Pe[DEPTH];
    float mk[DEPTH];
    float u = (r < 10) ? 1.f : 0.f;          // uniform burn-in start
    float acc = 0.f, ls_prev = 0.f;

    // prologue
    FETCH(0, t0 + 0) FETCH(1, t0 + 1) FETCH(2, t0 + 2) FETCH(3, t0 + 3)
    FETCH(4, t0 + 4) FETCH(5, t0 + 5) FETCH(6, t0 + 6) FETCH(7, t0 + 7)

    int t = t0;
    // ---- warm-up: 8 steps, no accumulation ----
    STEP(0, false, false, t + 0 + DEPTH)
    STEP(1, false, false, t + 1 + DEPTH)
    STEP(2, false, false, t + 2 + DEPTH)
    STEP(3, false, true,  t + 3 + DEPTH)
    STEP(4, false, false, t + 4 + DEPTH)
    STEP(5, false, false, t + 5 + DEPTH)
    STEP(6, false, false, t + 6 + DEPTH)
    STEP(7, false, true,  t + 7 + DEPTH)
    t += 8;

    // ---- phase switch: chunk 0 resets to exact initial distribution ----
    if (ci == 0) {
        u = (r < 10) ? u0v : u;
        ls_prev = ls0;
    }

    // ---- accumulate: CLEN steps ----
#pragma unroll 1
    for (int it = 0; it < CLEN / 8; ++it) {
        STEP(0, true, false, t + 0 + DEPTH)
        STEP(1, true, false, t + 1 + DEPTH)
        STEP(2, true, false, t + 2 + DEPTH)
        STEP(3, true, true,  t + 3 + DEPTH)
        STEP(4, true, false, t + 4 + DEPTH)
        STEP(5, true, false, t + 5 + DEPTH)
        STEP(6, true, false, t + 6 + DEPTH)
        STEP(7, true, true,  t + 7 + DEPTH)
        t += 8;
    }

    // ---- block partial + folded final reduction (deterministic order) ----
    if (r == 10) s_red[cl] = acc;
    __syncthreads();
    if (tid == 0) {
        float bs = (s_red[0] + s_red[1]) + (s_red[2] + s_red[3]);
        g_part[blockIdx.x] = bs;
        __threadfence();
        unsigned tk = atomicAdd(&g_done, 1);
        s_flag = (tk == NBLK - 1);
    }
    __syncthreads();
    if (s_flag) {
        __threadfence();
        float s = 0.f;
        for (int i = tid; i < NBLK; i += 64) s += g_part[i];
        s_sum[tid] = s;
        __syncthreads();
        for (int o = 32; o > 0; o >>= 1) {
            if (tid < o) s_sum[tid] += s_sum[tid + o];
            __syncthreads();
        }
        if (tid == 0) out[0] = s_sum[0] * 0.6931471805599453f;
    }
}

extern "C" void kernel_launch(void* const* d_in, const int* in_sizes, int n_in,
                              void* d_out, int out_size) {
    const int*   sent  = (const int*)d_in[0];
    const float* masks = (const float*)d_in[1];
    const float* emb   = (const float*)d_in[2];
    const float* trans = (const float*)d_in[3];
    const float* gw    = (const float*)d_in[4];
    const float* gb    = (const float*)d_in[5];
    const float* beg   = (const float*)d_in[6];
    float* out = (float*)d_out;

    k_collse<<<dim3(8, 10), 256>>>(emb);
    k_build<<<(2 * VOCAB + 255) / 256, 256>>>(emb, trans, gw, gb);
    k_scan<<<NBLK, 64>>>(sent, masks, beg, out);
}

// round 6
// speedup vs baseline: 1.1781x; 1.1781x over previous
#include <cuda_runtime.h>
#include <cuda_fp16.h>
#include <cuda_fp8.h>
#include <cstdint>

#define VOCAB 32000
#define NS 10
#define BB 256
#define TT 2048
#define CHUNKS 32
#define CLEN 64                 // TT / CHUNKS
#define WARM 8                  // burn-in steps (contraction ~0.27/step)
#define DEPTH 4                 // software pipeline depth
#define NGROUP (BB * CHUNKS)    // 8192 independent chains
#define NBLK (NGROUP / 4)       // 2048 blocks, 4 chains each
#define STAGE_N (WARM + CLEN + DEPTH)   // 76
#define LSE_BLOCKS 125          // VOCAB / 256

// Fused per-vocab table, fp8 e4m3, 128B-aligned rows (1 line, 4 sectors):
//  row layout: [8j .. 8j+8)   : col j, k=0..7 as 4 fp8x2 k-pairs   (j=0..10)
//              [88+2j..88+2j+2): col j, (k8,k9) fp8x2 pair
//  col j<10 : c[k][j] = E_v[k] * M_v[k][j];  col 10: E_v[k]
// E_v[k] = exp(emb[v,k]-colLSE[k]+15ln2); M_v = row-softmax(transition*f_v)
__device__ alignas(128) uint4 g_T8[VOCAB * 8];
__device__ float g_plse[10 * 128];   // per-block column partials
__device__ float g_lse[10];
__device__ float g_part[NBLK];
__device__ unsigned g_cnt_lse;       // ticket for k_collse finalizer
__device__ unsigned g_done;          // ticket for k_scan finalizer

// ---------------------------------------------------------------------------
// K1: column sums of exp(emb). 125 blocks x 256 threads; each block stages a
// 256-row tile via coalesced float4, one row per thread (static indices),
// warp butterfly + smem reduce; last block sums partials -> g_lse.
// ---------------------------------------------------------------------------
__global__ void __launch_bounds__(256) k_collse(const float* __restrict__ emb) {
    __shared__ float tile[2560];
    __shared__ float s_w[8][10];
    __shared__ bool s_last;

    int tid = threadIdx.x;
    const float4* src = (const float4*)(emb + blockIdx.x * 2560);
    float4* dst = (float4*)tile;
#pragma unroll
    for (int i = 0; i < 3; i++) {
        int idx = tid + i * 256;
        if (idx < 640) dst[idx] = src[idx];
    }
    __syncthreads();

    float p[10];
#pragma unroll
    for (int c = 0; c < 10; c++) p[c] = __expf(tile[tid * 10 + c]);
#pragma unroll
    for (int o = 16; o > 0; o >>= 1) {
#pragma unroll
        for (int c = 0; c < 10; c++)
            p[c] += __shfl_xor_sync(0xffffffffu, p[c], o);
    }
    int w = tid >> 5, l = tid & 31;
    if (l == 0) {
#pragma unroll
        for (int c = 0; c < 10; c++) s_w[w][c] = p[c];
    }
    __syncthreads();
    if (tid < 10) {
        float s = 0.f;
#pragma unroll
        for (int ww = 0; ww < 8; ww++) s += s_w[ww][tid];
        g_plse[tid * 128 + blockIdx.x] = s;
    }
    __threadfence();
    if (tid == 0) s_last = (atomicAdd(&g_cnt_lse, 1) == LSE_BLOCKS - 1);
    __syncthreads();
    if (s_last) {
        __threadfence();
        if (tid < 10) {
            float s = 0.f;
            for (int i = 0; i < LSE_BLOCKS; i++) s += g_plse[tid * 128 + i];
            g_lse[tid] = logf(s);
        }
        if (tid == 0) g_cnt_lse = 0;   // reset for next graph replay
    }
}

// exp(x) for |x| <= 0.5 (rel err ~3.6e-5)
__device__ __forceinline__ float exp_poly(float x) {
    float r = fmaf(x, 1.f / 120.f, 1.f / 24.f);
    r = fmaf(r, x, 1.f / 6.f);
    r = fmaf(r, x, 0.5f);
    r = fmaf(r, x, 1.f);
    r = fmaf(r, x, 1.f);
    return r;
}

__device__ __forceinline__ unsigned to_f8(float x) {
    return (unsigned)__nv_cvt_float_to_fp8(x, __NV_SATFINITE, __NV_E4M3);
}

// ---------------------------------------------------------------------------
// K2: build fused fp8 tables. 2 threads per vocab id.
// ---------------------------------------------------------------------------
__global__ void k_build(const float* __restrict__ emb,
                        const float* __restrict__ trans,
                        const float* __restrict__ gw,
                        const float* __restrict__ gb) {
    __shared__ float s_tr[100], s_gw[100], s_gb[10], s_lse[10];
    int tid = threadIdx.x;
    if (tid < 100) { s_tr[tid] = trans[tid]; s_gw[tid] = gw[tid]; }
    if (tid < 10) { s_gb[tid] = gb[tid]; s_lse[tid] = g_lse[tid]; }
    __syncthreads();

    int gidt = blockIdx.x * blockDim.x + tid;
    int v = gidt >> 1, half = gidt & 1;
    if (v >= VOCAB) return;

    float eb[10];
#pragma unroll
    for (int k = 0; k < 10; k++) eb[k] = emb[v * NS + k];

    const float LN2 = 0.6931471805599453f;
    float Ev[10];
#pragma unroll
    for (int j = 0; j < 10; j++)
        Ev[j] = __expf(eb[j] - s_lse[j] + 15.f * LN2);

    // gate: f_s = sigmoid(emb . gate_w[s,:] + gate_b[s])
    float f[10];
#pragma unroll
    for (int s = 0; s < 10; s++) {
        float g = s_gb[s];
#pragma unroll
        for (int k = 0; k < 10; k++) g = fmaf(eb[k], s_gw[s * 10 + k], g);
        f[s] = 1.f / (1.f + __expf(-g));
    }

    // row-softmax denominators fused with Ev
    float scale[10];
#pragma unroll
    for (int k = 0; k < 10; k++) {
        float rs = 0.f;
#pragma unroll
        for (int j = 0; j < 10; j++) rs += exp_poly(s_tr[k * 10 + j] * f[j]);
        scale[k] = Ev[k] * __fdividef(1.f, rs);
    }

    char* row = (char*)g_T8 + ((unsigned)v << 7);
    int j0 = half ? 5 : 0, j1 = half ? 10 : 5;
    for (int j = j0; j < j1; j++) {
        unsigned b[10];
#pragma unroll
        for (int k = 0; k < 10; k++)
            b[k] = to_f8(exp_poly(s_tr[k * 10 + j] * f[j]) * scale[k]);
        uint2 wv;
        wv.x = b[0] | (b[1] << 8) | (b[2] << 16) | (b[3] << 24);
        wv.y = b[4] | (b[5] << 8) | (b[6] << 16) | (b[7] << 24);
        *(uint2*)(row + 8 * j) = wv;
        *(unsigned short*)(row + 88 + 2 * j) = (unsigned short)(b[8] | (b[9] << 8));
    }
    if (half) {  // E column (j = 10)
        unsigned b[10];
#pragma unroll
        for (int k = 0; k < 10; k++) b[k] = to_f8(Ev[k]);
        uint2 wv;
        wv.x = b[0] | (b[1] << 8) | (b[2] << 16) | (b[3] << 24);
        wv.y = b[4] | (b[5] << 8) | (b[6] << 16) | (b[7] << 24);
        *(uint2*)(row + 80) = wv;
        *(unsigned short*)(row + 108) = (unsigned short)(b[8] | (b[9] << 8));
    }
}

// ---------------------------------------------------------------------------
// K3: chunked scan, half2 datapath. 64-thr blocks, 2 warps, 2 chains/warp
// (lanes 0-10 / 16-26). Lane r (<10): state u_r; lane r==10: S = Sum u_k E_k.
// CHUNKS=32 restores ~28 warps/SM to hide the half2 chain latency.
// ---------------------------------------------------------------------------
__device__ __forceinline__ __half2 f8h(unsigned s) {
    __half2_raw hr = __nv_cvt_fp8x2_to_halfraw2((__nv_fp8x2_storage_t)s, __NV_E4M3);
    return *(__half2*)&hr;
}

#define FETCH(st, t_)                                                        \
    {                                                                        \
        int2 tm_ = s_tm[cl][(t_) - t0];                                      \
        mk[st] = __int_as_float(tm_.y);                                      \
        if (act) {                                                           \
            const char* bp_ = (const char*)g_T8 + ((unsigned)tm_.x << 7);    \
            Pm[st] = *(const uint2*)(bp_ + 8 * r);                           \
            Pe[st] = *(const unsigned short*)(bp_ + 88 + 2 * r);             \
        }                                                                    \
    }

#define STEP(st, DOACC, DOREN, tn)                                           \
    {                                                                        \
        const unsigned FULL = 0xffffffffu;                                   \
        int sb_ = lane & 16;                                                 \
        float pu_ = __shfl_xor_sync(FULL, u, 1);                             \
        float lo_ = (lane & 1) ? pu_ : u;                                    \
        float hi_ = (lane & 1) ? u : pu_;                                    \
        __half2 hp_ = __floats2half2_rn(lo_, hi_);                           \
        unsigned hb_ = *(unsigned*)&hp_;                                     \
        unsigned H0 = __shfl_sync(FULL, hb_, sb_ + 0);                       \
        unsigned H1 = __shfl_sync(FULL, hb_, sb_ + 2);                       \
        unsigned H2 = __shfl_sync(FULL, hb_, sb_ + 4);                       \
        unsigned H3 = __shfl_sync(FULL, hb_, sb_ + 6);                       \
        unsigned H4 = __shfl_sync(FULL, hb_, sb_ + 8);                       \
        __half2 a_ = __hmul2(*(__half2*)&H0, f8h(Pm[st].x & 0xffffu));       \
        a_ = __hfma2(*(__half2*)&H1, f8h(Pm[st].x >> 16), a_);               \
        a_ = __hfma2(*(__half2*)&H2, f8h(Pm[st].y & 0xffffu), a_);           \
        a_ = __hfma2(*(__half2*)&H3, f8h(Pm[st].y >> 16), a_);               \
        a_ = __hfma2(*(__half2*)&H4, f8h((unsigned)Pe[st]), a_);             \
        float S = __half2float(__low2half(a_)) + __half2float(__high2half(a_)); \
        float ls = __log2f(S);                                               \
        if (DOACC) acc = fmaf(mk[st], (ls - ls_prev) - 15.0f, acc);          \
        if (DOREN) {                                                         \
            float sv = __shfl_sync(FULL, S, sb_ + 10);                       \
            int Ee = ((__float_as_int(sv) >> 23) & 255) - 127;               \
            u = S * __int_as_float((unsigned)(127 - Ee) << 23);              \
            ls_prev = ls - (float)Ee;                                        \
        } else {                                                             \
            u = S;                                                           \
            ls_prev = ls;                                                    \
        }                                                                    \
        FETCH(st, tn)                                                        \
    }

__global__ void __launch_bounds__(64)
k_scan(const int* __restrict__ sent, const float* __restrict__ masks,
       const float* __restrict__ beg, float* __restrict__ out) {
    __shared__ int2  s_tm[4][STAGE_N];
    __shared__ float s_red[4];
    __shared__ float s_sum[64];
    __shared__ bool  s_flag;

    int tid = threadIdx.x;
    int lane = tid & 31;
    int cl = tid >> 4;                       // chain-local id 0..3
    int r = lane & 15;

    // ---- stage tokens + masks for this block's 4 chains ----
    {
        int c = tid >> 4, i0 = tid & 15;
        int gid_c = blockIdx.x * 4 + c;
        int row_c = gid_c >> 5;              // / CHUNKS
        int t0_c = (gid_c & (CHUNKS - 1)) * CLEN - WARM;
        const int*   tr = sent  + (long)row_c * TT;
        const float* mr = masks + (long)row_c * TT;
        for (int i = i0; i < STAGE_N; i += 16) {
            int g = t0_c + i;
            g = (g < 0) ? 0 : ((g > TT - 1) ? TT - 1 : g);
            s_tm[c][i] = make_int2(tr[g], __float_as_int(mr[g]));
        }
    }
    __syncthreads();

    int gid = blockIdx.x * 4 + cl;
    int ci = gid & (CHUNKS - 1);
    int t0 = ci * CLEN - WARM;

    // exact start state for chunk 0
    float u0v = 0.f, s0 = 0.f;
#pragma unroll
    for (int j = 0; j < NS; j++) {
        float e = __expf(beg[j]);
        s0 += e;
        if (r == j) u0v = e;
    }
    float ls0 = __log2f(s0);

    const bool act = (r < 11);

    uint2 Pm[DEPTH];
    unsigned short Pe[DEPTH];
    float mk[DEPTH];
    float u = (r < 10) ? 1.f : 0.f;          // uniform burn-in start
    float acc = 0.f, ls_prev = 0.f;

    // prologue
    FETCH(0, t0 + 0) FETCH(1, t0 + 1) FETCH(2, t0 + 2) FETCH(3, t0 + 3)

    int t = t0;
    // ---- warm-up: 8 steps, no accumulation ----
    STEP(0, false, false, t + 0 + DEPTH)
    STEP(1, false, false, t + 1 + DEPTH)
    STEP(2, false, false, t + 2 + DEPTH)
    STEP(3, false, true,  t + 3 + DEPTH)
    STEP(0, false, false, t + 4 + DEPTH)
    STEP(1, false, false, t + 5 + DEPTH)
    STEP(2, false, false, t + 6 + DEPTH)
    STEP(3, false, true,  t + 7 + DEPTH)
    t += 8;

    // ---- phase switch: chunk 0 resets to exact initial distribution ----
    if (ci == 0) {
        u = (r < 10) ? u0v : u;
        ls_prev = ls0;
    }

    // ---- accumulate: CLEN steps ----
#pragma unroll 1
    for (int it = 0; it < CLEN / 8; ++it) {
        STEP(0, true, false, t + 0 + DEPTH)
        STEP(1, true, false, t + 1 + DEPTH)
        STEP(2, true, false, t + 2 + DEPTH)
        STEP(3, true, true,  t + 3 + DEPTH)
        STEP(0, true, false, t + 4 + DEPTH)
        STEP(1, true, false, t + 5 + DEPTH)
        STEP(2, true, false, t + 6 + DEPTH)
        STEP(3, true, true,  t + 7 + DEPTH)
        t += 8;
    }

    // ---- block partial + folded final reduction (deterministic order) ----
    if (r == 10) s_red[cl] = acc;
    __syncthreads();
    if (tid == 0) {
        float bs = (s_red[0] + s_red[1]) + (s_red[2] + s_red[3]);
        g_part[blockIdx.x] = bs;
        __threadfence();
        unsigned tk = atomicAdd(&g_done, 1);
        s_flag = (tk == NBLK - 1);
    }
    __syncthreads();
    if (s_flag) {
        __threadfence();
        float s = 0.f;
        for (int i = tid; i < NBLK; i += 64) s += g_part[i];
        s_sum[tid] = s;
        __syncthreads();
        for (int o = 32; o > 0; o >>= 1) {
            if (tid < o) s_sum[tid] += s_sum[tid + o];
            __syncthreads();
        }
        if (tid == 0) {
            out[0] = s_sum[0] * 0.6931471805599453f;
            g_done = 0;                      // reset for next graph replay
        }
    }
}

extern "C" void kernel_launch(void* const* d_in, const int* in_sizes, int n_in,
                              void* d_out, int out_size) {
    const int*   sent  = (const int*)d_in[0];
    const float* masks = (const float*)d_in[1];
    const float* emb   = (const float*)d_in[2];
    const float* trans = (const float*)d_in[3];
    const float* gw    = (const float*)d_in[4];
    const float* gb    = (const float*)d_in[5];
    const float* beg   = (const float*)d_in[6];
    float* out = (float*)d_out;

    k_collse<<<LSE_BLOCKS, 256>>>(emb);
    k_build<<<(2 * VOCAB + 255) / 256, 256>>>(emb, trans, gw, gb);
    k_scan<<<NBLK, 64>>>(sent, masks, beg, out);
}